// round 5
// baseline (speedup 1.0000x reference)
#include <cuda_runtime.h>
#include <cstdint>

// ---------------------------------------------------------------------------
// TreeCnnLayer: y[b,l,o] = relu( sum_{k=0..3} sum_i x[b, idx[l,k], i] * mask[k,i,o] + bias[127] )
// Gathered GEMM: M=131072, K=512, N=128.  mma.sync tf32 (plain sm_100 target).
// R5: ldmatrix.x4 for A and B^T fragments, 64x64 warp tiles, 2 CTAs/SM
//     (reg cap 256 -> no accumulator spills; (128,3) would cap at 170 and spill).
// ---------------------------------------------------------------------------

#define BATCH   16
#define NROWS   8192
#define TILE_M  128
#define NTILES  (NROWS / TILE_M)    // 64
#define BK      32
#define NCHUNK  16                  // 512 / 32
#define RPITCH  144                 // smem row pitch in bytes (36 floats)

#define STAGE_B   (128 * RPITCH)    // 18432 B (A and BT tiles identical shape)
#define SIDX_B    2048
#define SMEM_TOTAL (SIDX_B + 4 * STAGE_B)   // 75776

// W transposed + tf32-prerounded: g_WT[k][o][i] = rna_tf32(mask[k][i][o])
__device__ float g_WT[4 * 128 * 128];

__device__ __forceinline__ uint32_t smem_u32(const void* p) {
    uint32_t a;
    asm("{ .reg .u64 t; cvta.to.shared.u64 t, %1; cvt.u32.u64 %0, t; }" : "=r"(a) : "l"(p));
    return a;
}
__device__ __forceinline__ uint32_t f2tf32(float f) {
    uint32_t u;
    asm("cvt.rna.tf32.f32 %0, %1;" : "=r"(u) : "f"(f));
    return u;
}
__device__ __forceinline__ void cp_async16_cg(uint32_t dst, const void* src) {
    asm volatile("cp.async.cg.shared.global [%0], [%1], 16;" :: "r"(dst), "l"(src));
}
__device__ __forceinline__ void cp_async16_ca(uint32_t dst, const void* src) {
    asm volatile("cp.async.ca.shared.global [%0], [%1], 16;" :: "r"(dst), "l"(src));
}
__device__ __forceinline__ void ldsm_x4(uint32_t* r, uint32_t addr) {
    asm volatile("ldmatrix.sync.aligned.m8n8.x4.shared.b16 {%0,%1,%2,%3}, [%4];"
                 : "=r"(r[0]), "=r"(r[1]), "=r"(r[2]), "=r"(r[3]) : "r"(addr));
}
__device__ __forceinline__ void mma_tf32(float* d, const uint32_t* a, const uint32_t* b) {
    asm volatile(
        "mma.sync.aligned.m16n8k8.row.col.f32.tf32.tf32.f32 "
        "{%0,%1,%2,%3}, {%4,%5,%6,%7}, {%8,%9}, {%0,%1,%2,%3};"
        : "+f"(d[0]), "+f"(d[1]), "+f"(d[2]), "+f"(d[3])
        : "r"(a[0]), "r"(a[1]), "r"(a[2]), "r"(a[3]), "r"(b[0]), "r"(b[1]));
}

// ---------------- prep: transpose + round weights ----------------
__global__ void prep_w_kernel(const float* __restrict__ mask) {
    int t = blockIdx.x * blockDim.x + threadIdx.x;      // 65536
    int k = t >> 14, o = (t >> 7) & 127, i = t & 127;   // write-coalesced over i
    g_WT[t] = __uint_as_float(f2tf32(mask[(k << 14) + (i << 7) + o]));
}

// ---------------- main kernel ----------------
__global__ void __launch_bounds__(128, 2)
tree_gemm(const float* __restrict__ x, const float* __restrict__ bias,
          const int* __restrict__ itab32, float* __restrict__ out)
{
    extern __shared__ char smem[];
    int* sIdx = (int*)smem;
    const uint32_t sbase = smem_u32(smem);
    const uint32_t aBuf[2] = { sbase + SIDX_B,               sbase + SIDX_B + STAGE_B };
    const uint32_t bBuf[2] = { sbase + SIDX_B + 2 * STAGE_B, sbase + SIDX_B + 3 * STAGE_B };

    const int tid  = threadIdx.x;
    const int lane = tid & 31;
    const int wid  = tid >> 5;        // 4 warps: 2M x 2N
    const int wm   = wid >> 1;
    const int wn   = wid & 1;
    const int gr   = lane >> 2;
    const int qc   = lane & 3;
    const int b    = blockIdx.y;
    const int V    = blockIdx.x * TILE_M;

    // index dtype autodetect (int64 LE: word[1]=hi(tab[0,0])=0; int32: tab[0,1]=8191)
    const int istride = (itab32[1] == 0) ? 2 : 1;

    #pragma unroll
    for (int j = tid; j < 512; j += 128) {
        int k = j >> 7, r = j & 127;
        sIdx[j] = itab32[(size_t)(((V + r) << 2) + k) * istride];
    }
    __syncthreads();

    const char* xb = (const char*)(x + (size_t)b * NROWS * 128);

    // ldmatrix per-thread invariant offsets: matrix id 0..3, row-in-matrix 0..7
    const int m_id = lane >> 3, r_in = lane & 7;
    const uint32_t aOff = (uint32_t)((wm * 64 + r_in + ((m_id & 2) << 2)) * RPITCH + (m_id & 1) * 16);
    const uint32_t bOff = (uint32_t)((wn * 64 + r_in + ((m_id & 2) << 2)) * RPITCH + (m_id & 1) * 16);

    auto load_chunk = [&](int c, int st) {
        const int k  = c >> 2;
        const int c0 = (c & 3) * BK;
        // A: gathered rows, 128 x 32 floats; 1024 16B segs, 8 per thread
        #pragma unroll
        for (int i = 0; i < 8; i++) {
            int seg = tid + (i << 7);
            int r = seg >> 3, cs = seg & 7;
            int g = sIdx[(k << 7) + r];
            cp_async16_cg(aBuf[st] + r * RPITCH + cs * 16,
                          xb + (((size_t)g << 7) + c0 + (cs << 2)) * 4);
        }
        // BT: 128 o-rows x 32 i(k)-floats from g_WT[k][o][c0..c0+31]
        const char* wb = (const char*)g_WT + (((size_t)k << 14) + c0) * 4;
        #pragma unroll
        for (int i = 0; i < 8; i++) {
            int seg = tid + (i << 7);
            int r = seg >> 3, cs = seg & 7;
            cp_async16_ca(bBuf[st] + r * RPITCH + cs * 16,
                          wb + ((size_t)(r << 7) + (cs << 2)) * 4);
        }
        asm volatile("cp.async.commit_group;");
    };

    float acc[4][8][4];
    #pragma unroll
    for (int mf = 0; mf < 4; mf++)
        #pragma unroll
        for (int nf = 0; nf < 8; nf++)
            #pragma unroll
            for (int q = 0; q < 4; q++) acc[mf][nf][q] = 0.0f;

    load_chunk(0, 0);

    for (int c = 0; c < NCHUNK; c++) {
        if (c + 1 < NCHUNK) {
            load_chunk(c + 1, (c + 1) & 1);
            asm volatile("cp.async.wait_group 1;");
        } else {
            asm volatile("cp.async.wait_group 0;");
        }
        __syncthreads();

        const int st = c & 1;
        const uint32_t aB = aBuf[st] + aOff;
        const uint32_t bB = bBuf[st] + bOff;

        #pragma unroll
        for (int ks = 0; ks < 4; ks++) {
            const uint32_t ko = (uint32_t)(ks * 32);
            // A fragments: 4x LDSM.x4, then cvt.rna to tf32
            uint32_t a[4][4];
            #pragma unroll
            for (int mf = 0; mf < 4; mf++) {
                uint32_t r[4];
                ldsm_x4(r, aB + (uint32_t)(mf * 16 * RPITCH) + ko);
                // frag order: a0=m0, a1=m2, a2=m1, a3=m3
                a[mf][0] = f2tf32(__uint_as_float(r[0]));
                a[mf][1] = f2tf32(__uint_as_float(r[2]));
                a[mf][2] = f2tf32(__uint_as_float(r[1]));
                a[mf][3] = f2tf32(__uint_as_float(r[3]));
            }
            // B fragments (pre-rounded): 4x LDSM.x4, each covers 2 nf
            uint32_t bb[8][2];
            #pragma unroll
            for (int p = 0; p < 4; p++) {
                uint32_t r[4];
                ldsm_x4(r, bB + (uint32_t)(p * 16 * RPITCH) + ko);
                bb[2 * p][0]     = r[0];
                bb[2 * p][1]     = r[1];
                bb[2 * p + 1][0] = r[2];
                bb[2 * p + 1][1] = r[3];
            }
            #pragma unroll
            for (int mf = 0; mf < 4; mf++)
                #pragma unroll
                for (int nf = 0; nf < 8; nf++)
                    mma_tf32(acc[mf][nf], a[mf], bb[nf]);
        }
        __syncthreads();
    }

    // ---- epilogue: +bias[127], relu, store ----
    const float bv = bias[127];
    float* ob = out + ((size_t)b * NROWS + V + wm * 64) * 128 + wn * 64;

    #pragma unroll
    for (int mf = 0; mf < 4; mf++) {
        #pragma unroll
        for (int nf = 0; nf < 8; nf++) {
            int row = mf * 16 + gr;
            int col = nf * 8 + 2 * qc;
            float2 v0, v1;
            v0.x = fmaxf(acc[mf][nf][0] + bv, 0.0f);
            v0.y = fmaxf(acc[mf][nf][1] + bv, 0.0f);
            v1.x = fmaxf(acc[mf][nf][2] + bv, 0.0f);
            v1.y = fmaxf(acc[mf][nf][3] + bv, 0.0f);
            *(float2*)(ob + (size_t)row * 128 + col)       = v0;
            *(float2*)(ob + (size_t)(row + 8) * 128 + col) = v1;
        }
    }
}

// ---------------- launch ----------------
extern "C" void kernel_launch(void* const* d_in, const int* in_sizes, int n_in,
                              void* d_out, int out_size)
{
    const float* x = nullptr;
    const float* mask = nullptr;
    const float* bias = nullptr;
    const int*   itab = nullptr;
    for (int i = 0; i < n_in; i++) {
        switch (in_sizes[i]) {
            case 16777216: x    = (const float*)d_in[i]; break;
            case 65536:    mask = (const float*)d_in[i]; break;
            case 128:      bias = (const float*)d_in[i]; break;
            case 32768:    itab = (const int*)d_in[i];   break;
            default: break;
        }
    }
    float* out = (float*)d_out;

    cudaFuncSetAttribute(tree_gemm,
                         cudaFuncAttributeMaxDynamicSharedMemorySize, SMEM_TOTAL);

    prep_w_kernel<<<256, 256>>>(mask);

    dim3 grid(NTILES, BATCH);
    tree_gemm<<<grid, 128, SMEM_TOTAL>>>(x, bias, itab, out);
}